// round 16
// baseline (speedup 1.0000x reference)
#include <cuda_runtime.h>
#include <cstdint>

#define BATCH 8
#define NPTS  4096
#define CH    128
#define KNN   16
#define NDS   2048
#define CAP   48     // per-thread u16 stack capacity (slots)
#define QTR   (NPTS / 4)
#define QPB   128    // queries per block
#define TPB   512    // 4 threads per query
#define EPS   1e-3f  // conservative filter margin (>= 20x worst-case rounding slack)
#define SLOTB (TPB * 2)

// scratch (allocation-free rule: device globals)
__device__ float g_scores[BATCH * NPTS];
__device__ int   g_idx[BATCH * NDS];

// XLA:GPU small-row reduction order for a 16-element row (shfl_down 8,4,2,1)
__device__ __forceinline__ float tree16(const float* v) {
    float s8[8], s4[4], s2[2];
    #pragma unroll
    for (int l = 0; l < 8; ++l) s8[l] = __fadd_rn(v[l], v[l + 8]);
    #pragma unroll
    for (int l = 0; l < 4; ++l) s4[l] = __fadd_rn(s8[l], s8[l + 4]);
    #pragma unroll
    for (int l = 0; l < 2; ++l) s2[l] = __fadd_rn(s4[l], s4[l + 2]);
    return __fadd_rn(s2[0], s2[1]);
}

// Sentinel = mapped(+inf) in high word: unmaps back to +inf.
#define SENTINEL 0xFF800000FFFFFFFFull

// ---------------------------------------------------------------------------
// Kernel 1: per-point KNN score. FOUR threads per query (candidate quarters),
// verbatim R12 scan: approximate conservative filter (3 FFMA + FSETP):
//   lhs = sq_m - 2<p,q>  vs  rhs = (thr16 - sq_q) + EPS,
// unconditional STS + predicated byte-cursor advance; ballot-guarded flushes
// recompute EXACT d2 (verified sequence) into the exact sorted top-16
// (u64 (mapped_d2,idx) carry chain in registers). Quarters merged exactly at
// the end via a FULLY UNROLLED 3x16-key insert. launch_bounds(512,2) keeps
// regs <= 64 so 2 blocks stay resident per SM (grid was occupancy-limited).
// ---------------------------------------------------------------------------
__global__ void __launch_bounds__(TPB, 2) knn_score_kernel(const float* __restrict__ x) {
    extern __shared__ unsigned char smem[];
    float4* pts = (float4*)smem;                                   // 64KB
    const unsigned stkBase = (unsigned)(NPTS * 16);                // stacks: 48KB

    const int b   = blockIdx.y;
    const int tid = threadIdx.x;
    const int qt  = tid & (QPB - 1);   // query slot within block
    const int h   = tid >> 7;          // candidate quarter (0..3)
    const float* xb = x + b * 3 * NPTS;

    for (int m = tid; m < NPTS; m += TPB) {
        float v0 = xb[m], v1 = xb[NPTS + m], v2 = xb[2 * NPTS + m];
        float sq = __fadd_rn(__fadd_rn(__fmul_rn(v0, v0), __fmul_rn(v1, v1)),
                             __fmul_rn(v2, v2));
        pts[m] = make_float4(v0, v1, v2, sq);
    }
    __syncthreads();

    const int q = blockIdx.x * QPB + qt;
    const float4 me = pts[q];
    const float n2x = -2.0f * me.x, n2y = -2.0f * me.y, n2z = -2.0f * me.z;

    unsigned long long arr[KNN];
    #pragma unroll
    for (int k = 0; k < KNN; ++k) arr[k] = SENTINEL;
    float thrRHS = __int_as_float(0x7f800000);  // filter rhs = thr - sq_q + EPS

    const unsigned sp0 = stkBase + 2u * (unsigned)tid;
    unsigned sp = sp0;

    auto flush = [&]() {
        unsigned end = sp;
        for (unsigned j = sp0; j < end; j += SLOTB) {
            int m = *(const unsigned short*)(smem + j);
            float4 p = pts[m];
            float inner = fmaf(me.z, p.z, fmaf(me.y, p.y, __fmul_rn(me.x, p.x)));
            float t  = __fadd_rn(me.w, p.w);
            float d2 = fmaf(-2.0f, inner, t);  // EXACT verified sequence
            unsigned int ub = __float_as_uint(d2);
            ub ^= ((unsigned int)(((int)ub) >> 31)) | 0x80000000u;
            unsigned long long carry = ((unsigned long long)ub << 32) | (unsigned int)m;
            #pragma unroll
            for (int i = 0; i < KNN; ++i) {
                bool c = carry < arr[i];
                unsigned long long lo = c ? carry : arr[i];
                carry                 = c ? arr[i] : carry;
                arr[i] = lo;
            }
        }
        sp = sp0;
        unsigned int hb = (unsigned int)(arr[KNN - 1] >> 32);
        unsigned int uf = (hb & 0x80000000u) ? (hb ^ 0x80000000u) : ~hb;  // unmap
        float thrF = __uint_as_float(uf);
        thrRHS = (thrF - me.w) + EPS;
    };

    const unsigned spLimit = sp0 + (CAP - 32) * SLOTB;  // next chunk adds <= 32
    const int mbeg = h * QTR;
    for (int base = 0; base < QTR; base += 32) {
        if (__any_sync(0xffffffffu, sp > spLimit)) flush();
        #pragma unroll 32
        for (int mm = 0; mm < 32; ++mm) {
            int m = mbeg + base + mm;
            float4 p = pts[m];  // broadcast LDS.128
            // approximate conservative filter: 3 FFMA + FSETP
            float lhs = fmaf(p.x, n2x, fmaf(p.y, n2y, fmaf(p.z, n2z, p.w)));
            *(unsigned short*)(smem + sp) = (unsigned short)m;  // uncond STS
            sp += (lhs < thrRHS) ? SLOTB : 0;                   // pred advance
        }
    }
    flush();

    // merge: quarters 1..3 publish 16 keys each; quarter 0 inserts all 48
    // (fully unrolled). Region reuse: 48*128 u64 = 48KB = stack region.
    unsigned long long* mrg = (unsigned long long*)(smem + stkBase);
    __syncthreads();
    if (h != 0) {
        #pragma unroll
        for (int k = 0; k < KNN; ++k)
            mrg[((h - 1) * KNN + k) * QPB + qt] = arr[k];
    }
    __syncthreads();
    if (h == 0) {
        #pragma unroll
        for (int hh = 0; hh < 3; ++hh) {
            #pragma unroll
            for (int k = 0; k < KNN; ++k) {
                unsigned long long carry = mrg[(hh * KNN + k) * QPB + qt];
                #pragma unroll
                for (int i = 0; i < KNN; ++i) {
                    bool c = carry < arr[i];
                    unsigned long long lo = c ? carry : arr[i];
                    carry                 = c ? arr[i] : carry;
                    arr[i] = lo;
                }
            }
        }

        // arr sorted ascending by (d2, idx) == lax.top_k(-d2) order
        float4 nb[KNN];
        #pragma unroll
        for (int k = 0; k < KNN; ++k) nb[k] = pts[(unsigned int)arr[k]];

        // score: reduce k first (tree16 per coordinate), then sequentially over d
        float vx[KNN], vy[KNN], vz[KNN];
        #pragma unroll
        for (int k = 0; k < KNN; ++k) {
            float tx = __fsub_rn(nb[k].x, me.x);
            float ty = __fsub_rn(nb[k].y, me.y);
            float tz = __fsub_rn(nb[k].z, me.z);
            vx[k] = __fmul_rn(tx, tx);
            vy[k] = __fmul_rn(ty, ty);
            vz[k] = __fmul_rn(tz, tz);
        }
        float score = __fadd_rn(__fadd_rn(tree16(vx), tree16(vy)), tree16(vz));
        g_scores[b * NPTS + q] = score;
    }
}

// ---------------------------------------------------------------------------
// Kernel 2: per-batch bitonic sort of 4096 keys, compact pair indexing.
// key = (~mapped(score) << 32) | idx -> ascending u64 = desired rank order.
// ---------------------------------------------------------------------------
__global__ void __launch_bounds__(1024) sort_kernel() {
    __shared__ unsigned long long sh[NPTS];
    const int b = blockIdx.x, tid = threadIdx.x;

    for (int i = tid; i < NPTS; i += 1024) {
        unsigned int ub = __float_as_uint(g_scores[b * NPTS + i]);
        ub ^= ((unsigned int)(((int)ub) >> 31)) | 0x80000000u;
        sh[i] = (((unsigned long long)(~ub)) << 32) | (unsigned int)i;
    }
    __syncthreads();

    for (int k = 2; k <= NPTS; k <<= 1) {
        for (int j = k >> 1; j > 0; j >>= 1) {
            #pragma unroll 2
            for (int p = tid; p < NPTS / 2; p += 1024) {
                int i = ((p & ~(j - 1)) << 1) | (p & (j - 1));
                int l = i | j;
                unsigned long long Av = sh[i], Bv = sh[l];
                bool up = ((i & k) == 0);
                if ((Av > Bv) == up) { sh[i] = Bv; sh[l] = Av; }
            }
            __syncthreads();
        }
    }
    for (int j = tid; j < NDS; j += 1024)
        g_idx[b * NDS + j] = (int)(unsigned int)sh[j];
}

// ---------------------------------------------------------------------------
// Kernel 3: gather. out = [xyz (8*3*2048) | points (8*128*2048)]
// ---------------------------------------------------------------------------
__global__ void gather_kernel(const float* __restrict__ x,
                              const float* __restrict__ y,
                              float* __restrict__ out) {
    int t = blockIdx.x * blockDim.x + threadIdx.x;
    const int XYZ = BATCH * 3 * NDS;
    if (t < XYZ) {
        int j = t % NDS;
        int rest = t / NDS;
        int d = rest % 3;
        int b = rest / 3;
        int src = g_idx[b * NDS + j];
        out[t] = x[(b * 3 + d) * NPTS + src];
    } else {
        int t2 = t - XYZ;
        if (t2 < BATCH * CH * NDS) {
            int j = t2 % NDS;
            int rest = t2 / NDS;
            int c = rest % CH;
            int b = rest / CH;
            int src = g_idx[b * NDS + j];
            out[XYZ + t2] = y[(b * CH + c) * NPTS + src];
        }
    }
}

extern "C" void kernel_launch(void* const* d_in, const int* in_sizes, int n_in,
                              void* d_out, int out_size) {
    const float* x = (const float*)d_in[0];
    const float* y = (const float*)d_in[1];
    float* out = (float*)d_out;

    static const size_t kSmem = NPTS * 16 + CAP * TPB * 2;  // 112KB
    cudaFuncSetAttribute(knn_score_kernel,
                         cudaFuncAttributeMaxDynamicSharedMemorySize, (int)kSmem);

    dim3 gridA(NPTS / QPB, BATCH);
    knn_score_kernel<<<gridA, TPB, kSmem>>>(x);
    sort_kernel<<<BATCH, 1024>>>();

    const int total = BATCH * 3 * NDS + BATCH * CH * NDS;
    gather_kernel<<<(total + 255) / 256, 256>>>(x, y, out);
}

// round 17
// speedup vs baseline: 1.2705x; 1.2705x over previous
#include <cuda_runtime.h>
#include <cstdint>

#define BATCH 8
#define NPTS  4096
#define CH    128
#define KNN   16
#define NDS   2048
#define CAP   96    // per-thread u16 stack capacity
#define HALF  (NPTS / 2)
#define TPB   256
#define EPS   1e-3f // conservative filter margin (>= 20x worst-case rounding slack)

// scratch (allocation-free rule: device globals)
__device__ float g_scores[BATCH * NPTS];
__device__ int   g_idx[BATCH * NDS];

// XLA:GPU small-row reduction order for a 16-element row (shfl_down 8,4,2,1)
__device__ __forceinline__ float tree16(const float* v) {
    float s8[8], s4[4], s2[2];
    #pragma unroll
    for (int l = 0; l < 8; ++l) s8[l] = __fadd_rn(v[l], v[l + 8]);
    #pragma unroll
    for (int l = 0; l < 4; ++l) s4[l] = __fadd_rn(s8[l], s8[l + 4]);
    #pragma unroll
    for (int l = 0; l < 2; ++l) s2[l] = __fadd_rn(s4[l], s4[l + 2]);
    return __fadd_rn(s2[0], s2[1]);
}

// Sentinel = mapped(+inf) in high word: unmaps back to +inf.
#define SENTINEL 0xFF800000FFFFFFFFull

// ---------------------------------------------------------------------------
// Kernel 1: per-point KNN score. TWO threads per query (candidate halves).
// Identical to the verified 226.5us kernel EXCEPT the outer chunk loop is
// forced NON-UNROLLED (#pragma unroll 1) so the ~150-instr flush is inlined
// exactly once and total code stays I$-resident (~10KB vs ~100KB+ before).
// Hot loop: approximate conservative filter (3 FFMA + FSETP):
//   lhs = sq_m - 2<p,q>  vs  rhs = (thr16 - sq_q) + EPS
// -> unconditional STS + predicated byte-cursor advance. Rare flushes
// recompute EXACT d2 (verified sequence) into the exact sorted top-16
// (u64 (mapped_d2,idx) carry chain in registers). Halves merged exactly.
// ---------------------------------------------------------------------------
__global__ void __launch_bounds__(TPB) knn_score_kernel(const float* __restrict__ x) {
    extern __shared__ unsigned char smem[];
    float4* pts = (float4*)smem;                                   // 64KB
    const unsigned stkBase = (unsigned)(NPTS * 16);                // stacks: 48KB

    const int b   = blockIdx.y;
    const int tid = threadIdx.x;
    const int qt  = tid & 127;     // query slot within block
    const int h   = tid >> 7;      // candidate half
    const float* xb = x + b * 3 * NPTS;

    for (int m = tid; m < NPTS; m += TPB) {
        float v0 = xb[m], v1 = xb[NPTS + m], v2 = xb[2 * NPTS + m];
        float sq = __fadd_rn(__fadd_rn(__fmul_rn(v0, v0), __fmul_rn(v1, v1)),
                             __fmul_rn(v2, v2));
        pts[m] = make_float4(v0, v1, v2, sq);
    }
    __syncthreads();

    const int q = blockIdx.x * 128 + qt;
    const float4 me = pts[q];
    const float n2x = -2.0f * me.x, n2y = -2.0f * me.y, n2z = -2.0f * me.z;

    unsigned long long arr[KNN];
    #pragma unroll
    for (int k = 0; k < KNN; ++k) arr[k] = SENTINEL;
    float thrRHS = __int_as_float(0x7f800000);  // filter rhs = thr - sq_q + EPS

    // stack cursor: raw byte offset into smem; slot stride = TPB*2 bytes
    const unsigned sp0 = stkBase + 2u * (unsigned)tid;
    unsigned sp = sp0;

    auto flush = [&]() {
        unsigned end = sp;
        #pragma unroll 1
        for (unsigned j = sp0; j < end; j += TPB * 2) {
            int m = *(const unsigned short*)(smem + j);
            float4 p = pts[m];
            float inner = fmaf(me.z, p.z, fmaf(me.y, p.y, __fmul_rn(me.x, p.x)));
            float t  = __fadd_rn(me.w, p.w);
            float d2 = fmaf(-2.0f, inner, t);  // EXACT verified sequence
            unsigned int ub = __float_as_uint(d2);
            ub ^= ((unsigned int)(((int)ub) >> 31)) | 0x80000000u;
            unsigned long long carry = ((unsigned long long)ub << 32) | (unsigned int)m;
            #pragma unroll
            for (int i = 0; i < KNN; ++i) {
                bool c = carry < arr[i];
                unsigned long long lo = c ? carry : arr[i];
                carry                 = c ? arr[i] : carry;
                arr[i] = lo;
            }
        }
        sp = sp0;
        unsigned int hb = (unsigned int)(arr[KNN - 1] >> 32);
        unsigned int uf = (hb & 0x80000000u) ? (hb ^ 0x80000000u) : ~hb;  // unmap
        float thrF = __uint_as_float(uf);
        thrRHS = (thrF - me.w) + EPS;
    };

    const unsigned spLimit = sp0 + (CAP - 64) * (TPB * 2);
    const int mbeg = h * HALF;
    #pragma unroll 1
    for (int base = 0; base < HALF; base += 64) {
        if (__any_sync(0xffffffffu, sp > spLimit)) flush();
        #pragma unroll 32
        for (int mm = 0; mm < 64; ++mm) {
            int m = mbeg + base + mm;
            float4 p = pts[m];  // broadcast LDS.128
            // approximate conservative filter: 3 FFMA + FSETP
            float lhs = fmaf(p.x, n2x, fmaf(p.y, n2y, fmaf(p.z, n2z, p.w)));
            *(unsigned short*)(smem + sp) = (unsigned short)m;  // unconditional STS
            sp += (lhs < thrRHS) ? (TPB * 2) : 0;               // predicated advance
        }
    }
    flush();

    // merge: half-1 publishes its 16 keys, half-0 inserts them (exact union)
    unsigned long long* mrg = (unsigned long long*)(smem + stkBase);
    __syncthreads();
    if (h == 1) {
        #pragma unroll
        for (int k = 0; k < KNN; ++k) mrg[k * 128 + qt] = arr[k];
    }
    __syncthreads();
    if (h == 0) {
        #pragma unroll
        for (int k = 0; k < KNN; ++k) {
            unsigned long long carry = mrg[k * 128 + qt];
            #pragma unroll
            for (int i = 0; i < KNN; ++i) {
                bool c = carry < arr[i];
                unsigned long long lo = c ? carry : arr[i];
                carry                 = c ? arr[i] : carry;
                arr[i] = lo;
            }
        }

        // arr sorted ascending by (d2, idx) == lax.top_k(-d2) order
        float4 nb[KNN];
        #pragma unroll
        for (int k = 0; k < KNN; ++k) nb[k] = pts[(unsigned int)arr[k]];

        // score: reduce k first (tree16 per coordinate), then sequentially over d
        float vx[KNN], vy[KNN], vz[KNN];
        #pragma unroll
        for (int k = 0; k < KNN; ++k) {
            float tx = __fsub_rn(nb[k].x, me.x);
            float ty = __fsub_rn(nb[k].y, me.y);
            float tz = __fsub_rn(nb[k].z, me.z);
            vx[k] = __fmul_rn(tx, tx);
            vy[k] = __fmul_rn(ty, ty);
            vz[k] = __fmul_rn(tz, tz);
        }
        float score = __fadd_rn(__fadd_rn(tree16(vx), tree16(vy)), tree16(vz));
        g_scores[b * NPTS + q] = score;
    }
}

// ---------------------------------------------------------------------------
// Kernel 2: per-batch bitonic sort of 4096 keys, compact pair indexing.
// key = (~mapped(score) << 32) | idx -> ascending u64 = desired rank order.
// ---------------------------------------------------------------------------
__global__ void __launch_bounds__(1024) sort_kernel() {
    __shared__ unsigned long long sh[NPTS];
    const int b = blockIdx.x, tid = threadIdx.x;

    for (int i = tid; i < NPTS; i += 1024) {
        unsigned int ub = __float_as_uint(g_scores[b * NPTS + i]);
        ub ^= ((unsigned int)(((int)ub) >> 31)) | 0x80000000u;
        sh[i] = (((unsigned long long)(~ub)) << 32) | (unsigned int)i;
    }
    __syncthreads();

    for (int k = 2; k <= NPTS; k <<= 1) {
        for (int j = k >> 1; j > 0; j >>= 1) {
            #pragma unroll 2
            for (int p = tid; p < NPTS / 2; p += 1024) {
                int i = ((p & ~(j - 1)) << 1) | (p & (j - 1));
                int l = i | j;
                unsigned long long Av = sh[i], Bv = sh[l];
                bool up = ((i & k) == 0);
                if ((Av > Bv) == up) { sh[i] = Bv; sh[l] = Av; }
            }
            __syncthreads();
        }
    }
    for (int j = tid; j < NDS; j += 1024)
        g_idx[b * NDS + j] = (int)(unsigned int)sh[j];
}

// ---------------------------------------------------------------------------
// Kernel 3: gather. out = [xyz (8*3*2048) | points (8*128*2048)]
// ---------------------------------------------------------------------------
__global__ void gather_kernel(const float* __restrict__ x,
                              const float* __restrict__ y,
                              float* __restrict__ out) {
    int t = blockIdx.x * blockDim.x + threadIdx.x;
    const int XYZ = BATCH * 3 * NDS;
    if (t < XYZ) {
        int j = t % NDS;
        int rest = t / NDS;
        int d = rest % 3;
        int b = rest / 3;
        int src = g_idx[b * NDS + j];
        out[t] = x[(b * 3 + d) * NPTS + src];
    } else {
        int t2 = t - XYZ;
        if (t2 < BATCH * CH * NDS) {
            int j = t2 % NDS;
            int rest = t2 / NDS;
            int c = rest % CH;
            int b = rest / CH;
            int src = g_idx[b * NDS + j];
            out[XYZ + t2] = y[(b * CH + c) * NPTS + src];
        }
    }
}

extern "C" void kernel_launch(void* const* d_in, const int* in_sizes, int n_in,
                              void* d_out, int out_size) {
    const float* x = (const float*)d_in[0];
    const float* y = (const float*)d_in[1];
    float* out = (float*)d_out;

    static const size_t kSmem = NPTS * 16 + CAP * TPB * 2;  // 112KB
    cudaFuncSetAttribute(knn_score_kernel,
                         cudaFuncAttributeMaxDynamicSharedMemorySize, (int)kSmem);

    dim3 gridA(NPTS / 128, BATCH);
    knn_score_kernel<<<gridA, TPB, kSmem>>>(x);
    sort_kernel<<<BATCH, 1024>>>();

    const int total = BATCH * 3 * NDS + BATCH * CH * NDS;
    gather_kernel<<<(total + 255) / 256, 256>>>(x, y, out);
}